// round 16
// baseline (speedup 1.0000x reference)
#include <cuda_runtime.h>
#include <cuda_bf16.h>

// Shapes: query (N,T,C,L)=(32,64,256,64) fp32; key (T,N,C); out (T,N,C)
#define N_ 32
#define T_ 64
#define C_ 256
#define L_ 64
#define P_THRESH 1e-7f

__device__ float g_part[N_ * T_ * L_];   // per-(n,t) partial scores
__device__ float g_w[N_][L_];            // compact softmax weights
__device__ int   g_idx[N_][L_];          // compact l indices
__device__ int   g_cnt[N_];              // list length per n

// ---------------------------------------------------------------------------
// Kernel 1: partial scores (unchanged proven body, 24.4us @ ~73% DRAM).
// Streams q front-to-back -> q's TAIL ends L2-resident.
// ---------------------------------------------------------------------------
__global__ __launch_bounds__(256, 6) void k_scores(const float* __restrict__ q,
                                                   const float* __restrict__ key) {
    const int b = blockIdx.x;
    const int n = b >> 6;
    const int t = b & 63;
    const int w = threadIdx.x >> 5;
    const int lane = threadIdx.x & 31;
    const int half = lane >> 4;
    const int l4 = lane & 15;

    const float kreg = key[((size_t)t * N_ + n) * C_ + (w << 5) + lane];
    const float4* __restrict__ qb = reinterpret_cast<const float4*>(q);
    const size_t rowbase = (size_t)b * C_;

    float4 acc = make_float4(0.f, 0.f, 0.f, 0.f);
    #pragma unroll
    for (int i = 0; i < 16; ++i) {
        const int r = (i << 1) + half;
        const float kv = __shfl_sync(0xffffffffu, kreg, r);
        const float4 qv = qb[(rowbase + (w << 5) + r) * 16 + l4];
        acc.x = fmaf(kv, qv.x, acc.x);
        acc.y = fmaf(kv, qv.y, acc.y);
        acc.z = fmaf(kv, qv.z, acc.z);
        acc.w = fmaf(kv, qv.w, acc.w);
    }
    acc.x += __shfl_xor_sync(0xffffffffu, acc.x, 16);
    acc.y += __shfl_xor_sync(0xffffffffu, acc.y, 16);
    acc.z += __shfl_xor_sync(0xffffffffu, acc.z, 16);
    acc.w += __shfl_xor_sync(0xffffffffu, acc.w, 16);

    __shared__ float4 sm[8][16];
    if (half == 0) sm[w][l4] = acc;
    __syncthreads();
    if (threadIdx.x < 16) {
        float4 tot = sm[0][threadIdx.x];
        #pragma unroll
        for (int j = 1; j < 8; ++j) {
            const float4 v = sm[j][threadIdx.x];
            tot.x += v.x; tot.y += v.y; tot.z += v.z; tot.w += v.w;
        }
        reinterpret_cast<float4*>(g_part + (size_t)b * L_)[threadIdx.x] = tot;
    }
}

// ---------------------------------------------------------------------------
// Kernel 2: reduce over t + stable softmax + compaction (runs ONCE per n).
// 32 blocks x 64 threads. ~1.3us.
// ---------------------------------------------------------------------------
__global__ __launch_bounds__(64) void k_softmax() {
    const int n = blockIdx.x;
    const int l = threadIdx.x;
    const int w = l >> 5;
    const int lane = l & 31;

    float s = 0.f;
    const float* __restrict__ p = g_part + (size_t)n * T_ * L_ + l;
    #pragma unroll
    for (int t = 0; t < T_; ++t) s += p[(size_t)t * L_];

    float m = s;
    #pragma unroll
    for (int off = 16; off; off >>= 1)
        m = fmaxf(m, __shfl_xor_sync(0xffffffffu, m, off));
    __shared__ float wm[2];
    if (lane == 0) wm[w] = m;
    __syncthreads();
    m = fmaxf(wm[0], wm[1]);

    const float e = __expf(s - m);
    float sum = e;
    #pragma unroll
    for (int off = 16; off; off >>= 1)
        sum += __shfl_xor_sync(0xffffffffu, sum, off);
    __shared__ float ws[2];
    if (lane == 0) ws[w] = sum;
    __syncthreads();
    const float prob = e / (ws[0] + ws[1]);

    // deterministic compaction of significant weights
    const bool keep = prob > P_THRESH;
    const unsigned mask = __ballot_sync(0xffffffffu, keep);
    const int prefix = __popc(mask & ((1u << lane) - 1u));
    __shared__ int wcnt[2];
    if (lane == 0) wcnt[w] = __popc(mask);
    __syncthreads();
    const int base = (w == 1) ? wcnt[0] : 0;
    if (keep) {
        g_w[n][base + prefix] = prob;
        g_idx[n][base + prefix] = l;
    }
    if (l == 0) g_cnt[n] = wcnt[0] + wcnt[1];
}

// ---------------------------------------------------------------------------
// Kernel 3: pure sparse gather, REVERSED block order so its scattered reads
// target the L2-resident tail of q left by k_scores. Loads issue at cycle ~0
// (no pre-work). Thread tid == c; cnt is usually 1-2.
// ---------------------------------------------------------------------------
__global__ __launch_bounds__(256) void k_gather(const float* __restrict__ q,
                                                float* __restrict__ out) {
    const int b = (N_ * T_ - 1) - blockIdx.x;   // reversed for L2 reuse
    const int n = b >> 6;
    const int t = b & 63;
    const int c = threadIdx.x;

    const int m = g_cnt[n];
    const float* __restrict__ qrow = q + ((size_t)b * C_ + c) * L_;

    float acc = 0.f;
    #pragma unroll 2
    for (int j = 0; j < m; ++j)
        acc = fmaf(g_w[n][j], __ldg(qrow + g_idx[n][j]), acc);

    out[((size_t)t * N_ + n) * C_ + c] = acc;
}

extern "C" void kernel_launch(void* const* d_in, const int* in_sizes, int n_in,
                              void* d_out, int out_size) {
    const float* q   = (const float*)d_in[0];
    const float* key = (const float*)d_in[1];
    float* out = (float*)d_out;

    k_scores<<<N_ * T_, 256>>>(q, key);
    k_softmax<<<N_, 64>>>();
    k_gather<<<N_ * T_, 256>>>(q, out);
}